// round 7
// baseline (speedup 1.0000x reference)
#include <cuda_runtime.h>
#include <cstdint>

// ---------------- problem dims ----------------
#define BB 8
#define NN 256
#define NI 36
#define SS 64
#define IN_D 1024
#define QUE_D 1024
#define IMG_D 2048
#define SEM_D 512
#define PP 512
#define CATD 1536
#define OUTD 1024
#define ROWS (BB*NN)

// ---------------- scratch ----------------
__device__ float g_qproj_img[BB*PP];
__device__ float g_qproj_sem[BB*PP];
__device__ float g_np_img[ROWS*PP];
__device__ float g_np_sem[ROWS*PP];
__device__ float g_ip[BB*NI*PP];
__device__ float g_sp[BB*SS*PP];
__device__ float g_img_ctx[ROWS*IMG_D];
__device__ float g_sem_ctx[ROWS*SEM_D];
__device__ float g_cat[ROWS*CATD];
__device__ float g_gcat[ROWS*CATD];
// tf32-pre-rounded copies
__device__ float g_h_r[ROWS*IN_D];
__device__ float g_img_r[BB*NI*IMG_D];
__device__ float g_sem_r[BB*SS*SEM_D];
__device__ float g_Wcif_r[IN_D*PP];
__device__ float g_Wcsf_r[IN_D*PP];
__device__ float g_Wcii_r[IMG_D*PP];
__device__ float g_Wcsn_r[SEM_D*PP];
__device__ float g_Wfg_r[IN_D*PP];
__device__ float g_Wig_r[IMG_D*PP];
__device__ float g_Wsg_r[SEM_D*PP];
__device__ float g_Wgate_r[CATD*CATD];
__device__ float g_Wout_r[CATD*OUTD];

// ---------------- helpers ----------------
__device__ __forceinline__ float tanh_fast(float x) {
    float y;
    asm("tanh.approx.f32 %0, %1;" : "=f"(y) : "f"(x));
    return y;
}
__device__ __forceinline__ float sigmoid_fast(float x) {
    return 1.0f / (1.0f + __expf(-x));
}
__device__ __forceinline__ float f2tf_f(float x) {
    uint32_t r;
    asm("cvt.rna.tf32.f32 %0, %1;" : "=r"(r) : "f"(x));
    return __uint_as_float(r);
}
__device__ __forceinline__ void mma8(float* c, const uint32_t* a, uint32_t b0, uint32_t b1) {
    asm("mma.sync.aligned.m16n8k8.row.col.f32.tf32.tf32.f32 "
        "{%0,%1,%2,%3}, {%4,%5,%6,%7}, {%8,%9}, {%0,%1,%2,%3};"
        : "+f"(c[0]), "+f"(c[1]), "+f"(c[2]), "+f"(c[3])
        : "r"(a[0]), "r"(a[1]), "r"(a[2]), "r"(a[3]), "r"(b0), "r"(b1));
}
__device__ __forceinline__ uint32_t smem_u32(const void* p) {
    uint32_t a;
    asm("{ .reg .u64 t; cvta.to.shared.u64 t, %1; cvt.u32.u64 %0, t; }" : "=r"(a) : "l"(p));
    return a;
}
#define CP_ASYNC16(dst, src) \
    asm volatile("cp.async.cg.shared.global [%0], [%1], 16;" :: "r"(dst), "l"(src))
#define CP_COMMIT() asm volatile("cp.async.commit_group;" ::: "memory")
#define CP_WAIT1()  asm volatile("cp.async.wait_group 1;" ::: "memory")

// ---------------- tf32 pre-rounding ----------------
struct CvtList { const float* src[12]; float* dst[12]; int n4[12]; };
__global__ void cvt_prep(CvtList L) {
    int z = blockIdx.y;
    const float4* s = (const float4*)L.src[z];
    float4* d = (float4*)L.dst[z];
    int n4 = L.n4[z];
    for (int i = blockIdx.x * blockDim.x + threadIdx.x; i < n4; i += gridDim.x * blockDim.x) {
        float4 v = s[i];
        v.x = f2tf_f(v.x); v.y = f2tf_f(v.y); v.z = f2tf_f(v.z); v.w = f2tf_f(v.w);
        d[i] = v;
    }
}

// ---------------- batched tf32 MMA GEMM: 128 threads, warp tile 64x64 ----------------
// C[M,N] = A[M,K] @ W[K,N], operands pre-rounded tf32.
// mode 0: +bias; 1: +extra[(row>>8)*lde+col]; 2: sigmoid(acc+bias)*extra[row*lde+col]; rnd: tf32-round output.
// CTA 128x128, 4 warps of 64x64 (2x2), K stage 32, 3-stage cp.async, 1 sync/stage.
// A smem: 128 rows x 32 fl, chunk swizzle c^(row&7)          -> conflict-free frag LDS.
// B smem: 32 k-rows x 128 fl, chunk swizzle c^((k&3)<<1)     -> conflict-free frag LDS.
struct TaskDesc {
    const float* A; const float* W; const float* bias; const float* extra;
    float* C; int lda, ldw, lde, ldc, M, K, mode, rnd;
};

#define STG_FLOATS 8192          // 32KB/stage (A 16KB + B 16KB)
#define GEMM_SMEM (3 * STG_FLOATS * 4)

__global__ __launch_bounds__(128, 2)
void mma_gemm(TaskDesc t0, TaskDesc t1, TaskDesc t2) {
    TaskDesc T = (blockIdx.z == 0) ? t0 : (blockIdx.z == 1) ? t1 : t2;
    const int m0 = blockIdx.y * 128;
    if (m0 >= T.M) return;
    const int n0 = blockIdx.x * 128;

    extern __shared__ float sm[];
    const uint32_t smb = smem_u32(sm);

    const int tid = threadIdx.x;
    const int lane = tid & 31;
    const int wid = tid >> 5;            // 0..3
    const int wr = wid >> 1;             // 0..1 (m half)
    const int wc = wid & 1;              // 0..1 (n half)

    // ---- loader mappings (128 threads) ----
    const int arow = tid >> 2;           // A row 0..31 (+32s)
    const int acp  = (tid & 3) * 2;      // A chunk base (16B chunks, 8/row)
    const int bkr  = tid >> 4;           // B k-row 0..7 (+8s)
    const int bcp  = (tid & 15) * 2;     // B chunk base (32/row)

    uint32_t adst[4][2], bdst[4][2];
#pragma unroll
    for (int s = 0; s < 4; s++) {
        int row = arow + 32 * s;
#pragma unroll
        for (int j = 0; j < 2; j++)
            adst[s][j] = (uint32_t)(row * 128 + (((acp + j) ^ (row & 7)) << 4));
    }
#pragma unroll
    for (int s = 0; s < 4; s++) {
        int k = bkr + 8 * s;
#pragma unroll
        for (int j = 0; j < 2; j++)
            bdst[s][j] = (uint32_t)(16384 + k * 512 + (((bcp + j) ^ ((k & 3) << 1)) << 4));
    }
    const float* Asrc[4];
#pragma unroll
    for (int s = 0; s < 4; s++) {
        int r = m0 + arow + 32 * s;
        if (r >= T.M) r = T.M - 1;       // clamp; garbage discarded in epilogue
        Asrc[s] = T.A + (size_t)r * T.lda + acp * 4;
    }
    const float* Bsrc = T.W + (size_t)bkr * T.ldw + n0 + bcp * 4;

    const int S = T.K >> 5;

    auto issue_stage = [&](int i) {
        uint32_t base = smb + (uint32_t)(i % 3) * (STG_FLOATS * 4);
        int k0 = i << 5;
#pragma unroll
        for (int s = 0; s < 4; s++) {
            CP_ASYNC16(base + adst[s][0], Asrc[s] + k0);
            CP_ASYNC16(base + adst[s][1], Asrc[s] + k0 + 4);
        }
        const float* wsrc = Bsrc + (size_t)k0 * T.ldw;
#pragma unroll
        for (int s = 0; s < 4; s++) {
            const float* wr_ = wsrc + (size_t)(8 * s) * T.ldw;
            CP_ASYNC16(base + bdst[s][0], wr_);
            CP_ASYNC16(base + bdst[s][1], wr_ + 4);
        }
    };

    float acc[4][8][4];
#pragma unroll
    for (int i = 0; i < 4; i++)
#pragma unroll
        for (int t = 0; t < 8; t++)
#pragma unroll
            for (int r = 0; r < 4; r++) acc[i][t][r] = 0.0f;

    issue_stage(0); CP_COMMIT();
    if (S > 1) issue_stage(1);
    CP_COMMIT();

    const int lrow = lane >> 2;          // 0..7
    const int lk   = lane & 3;           // 0..3

    for (int i = 0; i < S; i++) {
        CP_WAIT1();
        __syncthreads();

        const float* base = sm + (size_t)(i % 3) * STG_FLOATS;
#pragma unroll
        for (int kk = 0; kk < 4; kk++) {
            uint32_t a[4][4], b[8][2];
#pragma unroll
            for (int ii = 0; ii < 4; ii++) {
                int mt = wr * 4 + ii;
#pragma unroll
                for (int r = 0; r < 4; r++) {
                    int row = mt * 16 + lrow + 8 * (r & 1);
                    int k = kk * 8 + lk + 4 * (r >> 1);
                    a[ii][r] = __float_as_uint(
                        base[row * 32 + (((k >> 2) ^ (row & 7)) << 2) + (k & 3)]);
                }
            }
#pragma unroll
            for (int t = 0; t < 8; t++) {
                int nt = wc * 8 + t;
#pragma unroll
                for (int r = 0; r < 2; r++) {
                    int k = kk * 8 + lk + 4 * r;
                    int n = nt * 8 + lrow;
                    b[t][r] = __float_as_uint(
                        base[4096 + k * 128 + (((n >> 2) ^ ((k & 3) << 1)) << 2) + (n & 3)]);
                }
            }
#pragma unroll
            for (int ii = 0; ii < 4; ii++)
#pragma unroll
                for (int t = 0; t < 8; t++)
                    mma8(acc[ii][t], a[ii], b[t][0], b[t][1]);
        }

        if (i + 2 < S) issue_stage(i + 2);
        CP_COMMIT();
    }

    // ---- epilogue ----
#pragma unroll
    for (int i = 0; i < 4; i++) {
        int rbase = m0 + wr * 64 + i * 16 + lrow;
#pragma unroll
        for (int t = 0; t < 8; t++) {
            int cb = n0 + wc * 64 + t * 8 + 2 * lk;
#pragma unroll
            for (int hh = 0; hh < 2; hh++) {
                int r = rbase + 8 * hh;
                if (r >= T.M) continue;
                float c0 = acc[i][t][2 * hh], c1 = acc[i][t][2 * hh + 1];
                float2 v;
                if (T.mode == 0) {
                    float2 bs = *(const float2*)(T.bias + cb);
                    v = make_float2(c0 + bs.x, c1 + bs.y);
                } else if (T.mode == 1) {
                    float2 ev = *(const float2*)(T.extra + (size_t)(r >> 8) * T.lde + cb);
                    v = make_float2(c0 + ev.x, c1 + ev.y);
                } else {
                    float2 bs = *(const float2*)(T.bias + cb);
                    float2 ev = *(const float2*)(T.extra + (size_t)r * T.lde + cb);
                    v = make_float2(sigmoid_fast(c0 + bs.x) * ev.x,
                                    sigmoid_fast(c1 + bs.y) * ev.y);
                }
                if (T.rnd) { v.x = f2tf_f(v.x); v.y = f2tf_f(v.y); }
                *(float2*)(T.C + (size_t)r * T.ldc + cb) = v;
            }
        }
    }
}

// ---------------- que projection (fp32 exact) ----------------
__global__ void qproj_kernel(const float* __restrict__ que,
                             const float* __restrict__ W1, const float* __restrict__ b1,
                             float* __restrict__ o1,
                             const float* __restrict__ W2, const float* __restrict__ b2,
                             float* __restrict__ o2) {
    const float* Wsub = (blockIdx.z == 0) ? W1 : W2;
    const float* bias = (blockIdx.z == 0) ? b1 : b2;
    float* out = (blockIdx.z == 0) ? o1 : o2;
    int b = blockIdx.y;
    int j = blockIdx.x * 128 + threadIdx.x;
    const float* q = que + b * QUE_D;
    float acc = bias[j];
#pragma unroll 4
    for (int k = 0; k < QUE_D; k++) acc += q[k] * Wsub[(size_t)k * PP + j];
    out[b * PP + j] = acc;
}

// ---------------- fused attention: 8 rows/block, ctx tf32-rounded ----------------
template <int KN, int D>
__global__ __launch_bounds__(256)
void att_kernel(const float* __restrict__ np_, const float* __restrict__ kp,
                const float* __restrict__ kv, const float* __restrict__ w,
                float* __restrict__ ctx) {
    __shared__ __align__(16) float s_w[PP];
    __shared__ float s_logit[8][64];
    __shared__ float s_att[8][64];

    const int g = blockIdx.x;
    const int b = g >> 5;
    const int r0 = (g & 31) * 8;
    const int tid = threadIdx.x;
    const int wid = tid >> 5, lane = tid & 31;

    for (int i = tid; i < PP; i += 256) s_w[i] = w[i];

    const int row = b * NN + r0 + wid;
    float4 npv[4];
    const float4* nr = (const float4*)(np_ + (size_t)row * PP);
#pragma unroll
    for (int i = 0; i < 4; i++) npv[i] = nr[lane + 32 * i];
    __syncthreads();

    for (int k = 0; k < KN; k++) {
        const float4* kr = (const float4*)(kp + (size_t)(b * KN + k) * PP);
        float acc = 0.0f;
#pragma unroll
        for (int i = 0; i < 4; i++) {
            float4 kv4 = kr[lane + 32 * i];
            float4 w4 = ((const float4*)s_w)[lane + 32 * i];
            acc = fmaf(tanh_fast(npv[i].x + kv4.x), w4.x, acc);
            acc = fmaf(tanh_fast(npv[i].y + kv4.y), w4.y, acc);
            acc = fmaf(tanh_fast(npv[i].z + kv4.z), w4.z, acc);
            acc = fmaf(tanh_fast(npv[i].w + kv4.w), w4.w, acc);
        }
#pragma unroll
        for (int o = 16; o > 0; o >>= 1) acc += __shfl_xor_sync(0xffffffff, acc, o);
        if (lane == 0) s_logit[wid][k] = acc;
    }
    __syncwarp();

    {
        float l0 = (lane < KN) ? s_logit[wid][lane] : -1e30f;
        float l1 = (lane + 32 < KN) ? s_logit[wid][lane + 32] : -1e30f;
        float m = fmaxf(l0, l1);
#pragma unroll
        for (int o = 16; o > 0; o >>= 1) m = fmaxf(m, __shfl_xor_sync(0xffffffff, m, o));
        float e0 = (lane < KN) ? __expf(l0 - m) : 0.0f;
        float e1 = (lane + 32 < KN) ? __expf(l1 - m) : 0.0f;
        float sum = e0 + e1;
#pragma unroll
        for (int o = 16; o > 0; o >>= 1) sum += __shfl_xor_sync(0xffffffff, sum, o);
        float inv = 1.0f / sum;
        s_att[wid][lane] = e0 * inv;
        if (lane + 32 < 64) s_att[wid][lane + 32] = e1 * inv;
    }
    __syncthreads();

    const float4* kvb = (const float4*)(kv + (size_t)b * KN * D);
    for (int d4 = tid; d4 < D / 4; d4 += 256) {
        float4 a[8];
#pragma unroll
        for (int r = 0; r < 8; r++) a[r] = make_float4(0.f, 0.f, 0.f, 0.f);
        for (int k = 0; k < KN; k++) {
            float4 v = kvb[(size_t)k * (D / 4) + d4];
#pragma unroll
            for (int r = 0; r < 8; r++) {
                float at = s_att[r][k];
                a[r].x = fmaf(at, v.x, a[r].x);
                a[r].y = fmaf(at, v.y, a[r].y);
                a[r].z = fmaf(at, v.z, a[r].z);
                a[r].w = fmaf(at, v.w, a[r].w);
            }
        }
#pragma unroll
        for (int r = 0; r < 8; r++) {
            float4 o;
            o.x = f2tf_f(a[r].x); o.y = f2tf_f(a[r].y);
            o.z = f2tf_f(a[r].z); o.w = f2tf_f(a[r].w);
            *(float4*)(ctx + (size_t)(b * NN + r0 + r) * D + d4 * 4) = o;
        }
    }
}

// ---------------- launch ----------------
extern "C" void kernel_launch(void* const* d_in, const int* in_sizes, int n_in,
                              void* d_out, int out_size) {
    const float* h      = (const float*)d_in[0];
    const float* img    = (const float*)d_in[1];
    const float* sem    = (const float*)d_in[2];
    const float* que    = (const float*)d_in[3];
    const float* W_cif  = (const float*)d_in[4];
    const float* b_cif  = (const float*)d_in[5];
    const float* W_cii  = (const float*)d_in[6];
    const float* b_cii  = (const float*)d_in[7];
    const float* w_ia   = (const float*)d_in[8];
    const float* W_csf  = (const float*)d_in[10];
    const float* b_csf  = (const float*)d_in[11];
    const float* W_csn  = (const float*)d_in[12];
    const float* b_csn  = (const float*)d_in[13];
    const float* w_sa   = (const float*)d_in[14];
    const float* W_ig   = (const float*)d_in[16];
    const float* b_ig   = (const float*)d_in[17];
    const float* W_sg   = (const float*)d_in[18];
    const float* b_sg   = (const float*)d_in[19];
    const float* W_fg   = (const float*)d_in[20];
    const float* b_fg   = (const float*)d_in[21];
    const float* W_gate = (const float*)d_in[22];
    const float* b_gate = (const float*)d_in[23];
    const float* W_out  = (const float*)d_in[24];
    const float* b_out  = (const float*)d_in[25];
    float* out = (float*)d_out;

    float *qpi, *qps, *npi, *nps, *ipb, *spb, *ictx, *sctx, *cat, *gcat;
    float *h_r, *img_r, *sem_r;
    float *Wcif_r, *Wcsf_r, *Wcii_r, *Wcsn_r, *Wfg_r, *Wig_r, *Wsg_r, *Wgate_r, *Wout_r;
    cudaGetSymbolAddress((void**)&qpi,  g_qproj_img);
    cudaGetSymbolAddress((void**)&qps,  g_qproj_sem);
    cudaGetSymbolAddress((void**)&npi,  g_np_img);
    cudaGetSymbolAddress((void**)&nps,  g_np_sem);
    cudaGetSymbolAddress((void**)&ipb,  g_ip);
    cudaGetSymbolAddress((void**)&spb,  g_sp);
    cudaGetSymbolAddress((void**)&ictx, g_img_ctx);
    cudaGetSymbolAddress((void**)&sctx, g_sem_ctx);
    cudaGetSymbolAddress((void**)&cat,  g_cat);
    cudaGetSymbolAddress((void**)&gcat, g_gcat);
    cudaGetSymbolAddress((void**)&h_r,    g_h_r);
    cudaGetSymbolAddress((void**)&img_r,  g_img_r);
    cudaGetSymbolAddress((void**)&sem_r,  g_sem_r);
    cudaGetSymbolAddress((void**)&Wcif_r, g_Wcif_r);
    cudaGetSymbolAddress((void**)&Wcsf_r, g_Wcsf_r);
    cudaGetSymbolAddress((void**)&Wcii_r, g_Wcii_r);
    cudaGetSymbolAddress((void**)&Wcsn_r, g_Wcsn_r);
    cudaGetSymbolAddress((void**)&Wfg_r,  g_Wfg_r);
    cudaGetSymbolAddress((void**)&Wig_r,  g_Wig_r);
    cudaGetSymbolAddress((void**)&Wsg_r,  g_Wsg_r);
    cudaGetSymbolAddress((void**)&Wgate_r,g_Wgate_r);
    cudaGetSymbolAddress((void**)&Wout_r, g_Wout_r);

    static bool attr_set = false;
    if (!attr_set) {
        cudaFuncSetAttribute(mma_gemm, cudaFuncAttributeMaxDynamicSharedMemorySize, GEMM_SMEM);
        attr_set = true;
    }

    // 1: tf32 pre-round
    {
        CvtList L;
        L.src[0] = h;      L.dst[0] = h_r;    L.n4[0] = ROWS*IN_D/4;
        L.src[1] = img;    L.dst[1] = img_r;  L.n4[1] = BB*NI*IMG_D/4;
        L.src[2] = sem;    L.dst[2] = sem_r;  L.n4[2] = BB*SS*SEM_D/4;
        L.src[3] = W_cif;  L.dst[3] = Wcif_r; L.n4[3] = IN_D*PP/4;
        L.src[4] = W_csf;  L.dst[4] = Wcsf_r; L.n4[4] = IN_D*PP/4;
        L.src[5] = W_cii;  L.dst[5] = Wcii_r; L.n4[5] = IMG_D*PP/4;
        L.src[6] = W_csn;  L.dst[6] = Wcsn_r; L.n4[6] = SEM_D*PP/4;
        L.src[7] = W_fg;   L.dst[7] = Wfg_r;  L.n4[7] = IN_D*PP/4;
        L.src[8] = W_ig;   L.dst[8] = Wig_r;  L.n4[8] = IMG_D*PP/4;
        L.src[9] = W_sg;   L.dst[9] = Wsg_r;  L.n4[9] = SEM_D*PP/4;
        L.src[10]= W_gate; L.dst[10]= Wgate_r;L.n4[10]= CATD*CATD/4;
        L.src[11]= W_out;  L.dst[11]= Wout_r; L.n4[11]= CATD*OUTD/4;
        cvt_prep<<<dim3(148, 12), 256>>>(L);
    }
    // 2: que projections
    qproj_kernel<<<dim3(PP/128, BB, 2), 128>>>(que, W_cif + (size_t)IN_D * PP, b_cif, qpi,
                                               W_csf + (size_t)IN_D * PP, b_csf, qps);
    // 3: ip + sp
    {
        TaskDesc ta  = { img_r, Wcii_r, b_cii, nullptr, ipb, IMG_D, PP, 0, PP, BB*NI, IMG_D, 0, 0 };
        TaskDesc tb2 = { sem_r, Wcsn_r, b_csn, nullptr, spb, SEM_D, PP, 0, PP, BB*SS, SEM_D, 0, 0 };
        mma_gemm<<<dim3(PP/128, 4, 2), 128, GEMM_SMEM>>>(ta, tb2, ta);
    }
    // 4: np pair  <-- profiled slot
    {
        TaskDesc ta  = { h_r, Wcif_r, nullptr, qpi, npi, IN_D, PP, PP, PP, ROWS, IN_D, 1, 0 };
        TaskDesc tb2 = { h_r, Wcsf_r, nullptr, qps, nps, IN_D, PP, PP, PP, ROWS, IN_D, 1, 0 };
        mma_gemm<<<dim3(PP/128, ROWS/128, 2), 128, GEMM_SMEM>>>(ta, tb2, ta);
    }
    // 5,6: fused attention
    att_kernel<NI, IMG_D><<<BB * (NN/8), 256>>>(npi, ipb, img, w_ia, ictx);
    att_kernel<SS, SEM_D><<<BB * (NN/8), 256>>>(nps, spb, sem, w_sa, sctx);
    // 7: cat projections
    {
        TaskDesc ta  = { h_r,  Wfg_r, b_fg, nullptr, cat,        IN_D,  PP, 0, CATD, ROWS, IN_D,  0, 1 };
        TaskDesc tb2 = { ictx, Wig_r, b_ig, nullptr, cat + PP,   IMG_D, PP, 0, CATD, ROWS, IMG_D, 0, 1 };
        TaskDesc tc  = { sctx, Wsg_r, b_sg, nullptr, cat + 2*PP, SEM_D, PP, 0, CATD, ROWS, SEM_D, 0, 1 };
        mma_gemm<<<dim3(PP/128, ROWS/128, 3), 128, GEMM_SMEM>>>(ta, tb2, tc);
    }
    // 8: gate
    {
        TaskDesc ta = { cat, Wgate_r, b_gate, cat, gcat, CATD, CATD, CATD, CATD, ROWS, CATD, 2, 1 };
        mma_gemm<<<dim3(CATD/128, ROWS/128, 1), 128, GEMM_SMEM>>>(ta, ta, ta);
    }
    // 9: out
    {
        TaskDesc ta = { gcat, Wout_r, b_out, nullptr, out, CATD, OUTD, 0, OUTD, ROWS, CATD, 0, 0 };
        mma_gemm<<<dim3(OUTD/128, ROWS/128, 1), 128, GEMM_SMEM>>>(ta, ta, ta);
    }
}